// round 9
// baseline (speedup 1.0000x reference)
#include <cuda_runtime.h>

#define B_    16
#define C_    256
#define H_    56
#define W_    56
#define HW_   3136
#define NP_   50176   // B_*HW_
#define MID_  64
#define OC2_  144     // KK * GROUPS = 9 * 16

// scratch for per-pixel kernels, GLOBAL-PIXEL layout: [144][50176]  (~28.9 MB)
__device__ float g_weight[OC2_ * NP_];

// ---- packed f32x2 helpers ------------------------------------------------
typedef unsigned long long ull;

__device__ __forceinline__ ull pack2(float lo, float hi) {
    ull r;
    asm("mov.b64 %0, {%1, %2};" : "=l"(r) : "f"(lo), "f"(hi));
    return r;
}
__device__ __forceinline__ void unpack2(ull v, float& lo, float& hi) {
    asm("mov.b64 {%0, %1}, %2;" : "=f"(lo), "=f"(hi) : "l"(v));
}
__device__ __forceinline__ void ffma2(ull& d, ull a, ull b) {
    asm("fma.rn.f32x2 %0, %1, %2, %0;" : "+l"(d) : "l"(a), "l"(b));
}

union F4U2 { float4 f; ull u[2]; };

// ---------------------------------------------------------------------------
// Kernel 1: fused  conv1(1x1) + BN + ReLU + conv2(1x1) + bias
// 128 threads, one block = 128 global pixels (may straddle image boundary).
// Stage 1: t[64][128px]  = w1[64x256] * x[256][128px]  (8mid x 8px, FFMA2)
// Stage 2: w [144][128px]= w2[144x64] * t + b2         (6o2 x 8px, 3 passes)
// smem union (48 KB exactly): {As 8K + Bs 16K} <-> {Ts 32K + W2s 16K}
// ---------------------------------------------------------------------------
__global__ __launch_bounds__(128) void fused_conv_kernel(
    const float* __restrict__ x,
    const float* __restrict__ w1,
    const float* __restrict__ bn_gamma,
    const float* __restrict__ bn_beta,
    const float* __restrict__ bn_mean,
    const float* __restrict__ bn_var,
    const float* __restrict__ w2,
    const float* __restrict__ b2)
{
    __shared__ __align__(16) float smem_buf[12288];    // 48 KB
    float (*As)[64]   = (float(*)[64])  smem_buf;            // [32k][64o]
    float (*Bs)[128]  = (float(*)[128])(smem_buf + 2048);    // [32k][128p]
    float (*Ts)[128]  = (float(*)[128]) smem_buf;            // [64mid][128p]
    float (*W2s)[64]  = (float(*)[64]) (smem_buf + 8192);    // [64k][48slot(pad8)]

    const int tid = threadIdx.x;
    const int p0  = blockIdx.x * 128;          // global pixel base
    const int b0  = p0 / HW_;
    const int hwb = p0 - b0 * HW_;
    const int bnd = HW_ - hwb;                 // pixels >= bnd belong to b0+1

    const int ps  = tid & 15;                  // pixel slot
    const int px0 = ps * 8;                    // 8 consecutive pixels
    const int ms  = tid >> 4;                  // mid-slot 0..7

    // acc[i][jp]: mid ms*8+i, pixel pair (px0+2jp, px0+2jp+1)
    ull accp[8][4];
    #pragma unroll
    for (int i = 0; i < 8; i++)
        #pragma unroll
        for (int j = 0; j < 4; j++) accp[i][j] = 0ull;

    const int o_a = tid & 63;
    const int kh  = tid >> 6;                  // 0..1

    for (int kt = 0; kt < C_; kt += 32) {
        // load w1 tile transposed: As[k][o]
        #pragma unroll
        for (int q = 0; q < 4; q++) {
            float4 v = *(const float4*)&w1[o_a * C_ + kt + kh * 16 + q * 4];
            As[kh * 16 + q * 4 + 0][o_a] = v.x;
            As[kh * 16 + q * 4 + 1][o_a] = v.y;
            As[kh * 16 + q * 4 + 2][o_a] = v.z;
            As[kh * 16 + q * 4 + 3][o_a] = v.w;
        }
        // load x tile: Bs[k][p] (handle image-boundary straddle per float4)
        #pragma unroll
        for (int j = 0; j < 8; j++) {
            int f4i = tid + 128 * j;
            int kc  = f4i >> 5;
            int q4  = (f4i & 31) * 4;
            int ov  = (q4 >= bnd);
            int bb  = b0 + ov;
            int hw  = ov ? (q4 - bnd) : (hwb + q4);
            *(float4*)&Bs[kc][q4] =
                *(const float4*)&x[((size_t)bb * C_ + kt + kc) * HW_ + hw];
        }
        __syncthreads();

        #pragma unroll 8
        for (int kc = 0; kc < 32; kc++) {
            F4U2 B0, B1;
            B0.f = *(const float4*)&Bs[kc][px0];
            B1.f = *(const float4*)&Bs[kc][px0 + 4];
            ull tp[4] = {B0.u[0], B0.u[1], B1.u[0], B1.u[1]};
            float4 a0 = *(const float4*)&As[kc][ms * 8];
            float4 a1 = *(const float4*)&As[kc][ms * 8 + 4];
            float av[8] = {a0.x, a0.y, a0.z, a0.w, a1.x, a1.y, a1.z, a1.w};
            #pragma unroll
            for (int i = 0; i < 8; i++) {
                ull ap = pack2(av[i], av[i]);
                #pragma unroll
                for (int jp = 0; jp < 4; jp++)
                    ffma2(accp[i][jp], ap, tp[jp]);
            }
        }
        __syncthreads();
    }

    // BN (eval) + ReLU epilogue -> Ts  (Ts aliases As/Bs; all reads done)
    #pragma unroll
    for (int i = 0; i < 8; i++) {
        int o = ms * 8 + i;
        float s  = bn_gamma[o] * rsqrtf(bn_var[o] + 1e-5f);
        float sh = bn_beta[o] - bn_mean[o] * s;
        float t[8];
        #pragma unroll
        for (int jp = 0; jp < 4; jp++) {
            float lo, hi;
            unpack2(accp[i][jp], lo, hi);
            t[2 * jp]     = fmaxf(fmaf(lo, s, sh), 0.f);
            t[2 * jp + 1] = fmaxf(fmaf(hi, s, sh), 0.f);
        }
        *(float4*)&Ts[o][px0]     = make_float4(t[0], t[1], t[2], t[3]);
        *(float4*)&Ts[o][px0 + 4] = make_float4(t[4], t[5], t[6], t[7]);
    }
    __syncthreads();

    // Stage 2: three passes over 48 output rows each
    const int os = ms;                         // o2 slot group 0..7

    for (int rr = 0; rr < 3; rr++) {
        // load w2 slice transposed into W2s[k][(lr/6)*8 + lr%6]
        #pragma unroll
        for (int j = 0; j < 6; j++) {
            int lr = (tid & 15) + 16 * (j % 3);       // 0..47
            int kq = (tid >> 4) + 8 * (j / 3);        // 0..15
            int k4 = kq * 4;
            int msl = lr / 6, ii = lr - msl * 6;
            int o2 = msl * 18 + rr * 6 + ii;
            float4 v = *(const float4*)&w2[o2 * MID_ + k4];
            int lslot = msl * 8 + ii;
            W2s[k4 + 0][lslot] = v.x;
            W2s[k4 + 1][lslot] = v.y;
            W2s[k4 + 2][lslot] = v.z;
            W2s[k4 + 3][lslot] = v.w;
        }
        __syncthreads();

        // accq[ii][jp]: o2 = os*18 + rr*6 + ii, pixel pair (px0+2jp, ...)
        ull accq[6][4];
        #pragma unroll
        for (int q = 0; q < 6; q++)
            #pragma unroll
            for (int j = 0; j < 4; j++) accq[q][j] = 0ull;

        #pragma unroll 8
        for (int k = 0; k < MID_; k++) {
            F4U2 T0, T1;
            T0.f = *(const float4*)&Ts[k][px0];
            T1.f = *(const float4*)&Ts[k][px0 + 4];
            ull tp[4] = {T0.u[0], T0.u[1], T1.u[0], T1.u[1]};
            float4 wa = *(const float4*)&W2s[k][os * 8];
            float2 wb = *(const float2*)&W2s[k][os * 8 + 4];
            float wv[6] = {wa.x, wa.y, wa.z, wa.w, wb.x, wb.y};
            #pragma unroll
            for (int ii = 0; ii < 6; ii++) {
                ull wp = pack2(wv[ii], wv[ii]);
                #pragma unroll
                for (int jp = 0; jp < 4; jp++)
                    ffma2(accq[ii][jp], wp, tp[jp]);
            }
        }

        #pragma unroll
        for (int ii = 0; ii < 6; ii++) {
            int o2 = os * 18 + rr * 6 + ii;
            float bias = b2[o2];
            float o8[8];
            #pragma unroll
            for (int jp = 0; jp < 4; jp++) {
                float lo, hi;
                unpack2(accq[ii][jp], lo, hi);
                o8[2 * jp]     = lo + bias;
                o8[2 * jp + 1] = hi + bias;
            }
            float* wout = g_weight + (size_t)o2 * NP_ + p0 + px0;
            *(float4*)&wout[0] = make_float4(o8[0], o8[1], o8[2], o8[3]);
            *(float4*)&wout[4] = make_float4(o8[4], o8[5], o8[6], o8[7]);
        }
        __syncthreads();
    }
}

// ---------------------------------------------------------------------------
// Kernel 2: involution. Block = (4-row tile, group g, b). 256 threads:
// slot = tid&15 (col quad, 14 active), r = (tid>>4)&3 (row), cq = tid>>6
// (channel quad). Each thread: 9 kernel float4s cached in registers, reused
// across 4 channels -> weight LDS amortized 4x, zero index ALU in hot loop.
// ---------------------------------------------------------------------------
__global__ __launch_bounds__(256) void involution_kernel(
    const float* __restrict__ x,
    float* __restrict__ out)
{
    __shared__ float ws[9][224];      // [kk][r*56+col], 4 rows contiguous   8.1 KB
    __shared__ float xs[6][16][60];   // [y0-1..y0+4][ch][col -1..58]       23.0 KB

    const int y0  = blockIdx.x * 4;
    const int g   = blockIdx.y;
    const int b   = blockIdx.z;
    const int tid = threadIdx.x;
    const int warp = tid >> 5, lane = tid & 31;

    // x halo: 6 rows x 16 channels x 58 cols (zero-padded edges)
    const float* xsrc = x + ((size_t)(b * C_ + g * 16)) * HW_;
    for (int seg = warp; seg < 96; seg += 8) {
        int row = seg >> 4, c = seg & 15;
        int gy = y0 + row - 1;
        bool rowok = ((unsigned)gy < (unsigned)H_);
        const float* src = xsrc + (size_t)c * HW_ + gy * W_;
        #pragma unroll
        for (int q = 0; q < 2; q++) {
            int col = lane + q * 32;
            if (col < 60) {
                int gx = col - 1;
                float v = 0.f;
                if (rowok && (unsigned)gx < (unsigned)W_) v = src[gx];
                xs[row][c][col] = v;
            }
        }
    }
    // per-pixel kernels: 9 kk, rows y0..y0+3 = 224 contiguous floats each
    const float* wsrc = g_weight + (size_t)(g * 9) * NP_ + b * HW_ + y0 * W_;
    for (int kk = warp; kk < 9; kk += 8) {
        #pragma unroll
        for (int q = 0; q < 7; q++) {
            int col = lane + q * 32;
            ws[kk][col] = wsrc[(size_t)kk * NP_ + col];
        }
    }
    __syncthreads();

    const int slot = tid & 15;
    const int r    = (tid >> 4) & 3;
    const int cq   = tid >> 6;
    if (slot >= 14) return;
    const int x0 = slot * 4;
    const int wb = r * 56 + x0;

    // cache this thread's 9 kernel weight quads in registers
    float4 wv[9];
    #pragma unroll
    for (int kk = 0; kk < 9; kk++)
        wv[kk] = *(const float4*)&ws[kk][wb];

    float* outb = out + ((size_t)(b * C_ + g * 16 + cq * 4)) * HW_
                + (y0 + r) * W_ + x0;

    #pragma unroll
    for (int c = 0; c < 4; c++) {
        const int ch = cq * 4 + c;
        float a0 = 0.f, a1 = 0.f, a2 = 0.f, a3 = 0.f;
        #pragma unroll
        for (int dr = 0; dr < 3; dr++) {
            const float* xr = &xs[r + dr][ch][x0];
            float4 v4 = *(const float4*)xr;
            float2 v2 = *(const float2*)(xr + 4);

            float4 w0 = wv[dr * 3 + 0];
            a0 = fmaf(w0.x, v4.x, a0);
            a1 = fmaf(w0.y, v4.y, a1);
            a2 = fmaf(w0.z, v4.z, a2);
            a3 = fmaf(w0.w, v4.w, a3);

            float4 w1_ = wv[dr * 3 + 1];
            a0 = fmaf(w1_.x, v4.y, a0);
            a1 = fmaf(w1_.y, v4.z, a1);
            a2 = fmaf(w1_.z, v4.w, a2);
            a3 = fmaf(w1_.w, v2.x, a3);

            float4 w2_ = wv[dr * 3 + 2];
            a0 = fmaf(w2_.x, v4.z, a0);
            a1 = fmaf(w2_.y, v4.w, a1);
            a2 = fmaf(w2_.z, v2.x, a2);
            a3 = fmaf(w2_.w, v2.y, a3);
        }
        *(float4*)&outb[(size_t)c * HW_] = make_float4(a0, a1, a2, a3);
    }
}

extern "C" void kernel_launch(void* const* d_in, const int* in_sizes, int n_in,
                              void* d_out, int out_size)
{
    const float* x        = (const float*)d_in[0];
    const float* w1       = (const float*)d_in[1];
    const float* bn_gamma = (const float*)d_in[2];
    const float* bn_beta  = (const float*)d_in[3];
    const float* bn_mean  = (const float*)d_in[4];
    const float* bn_var   = (const float*)d_in[5];
    const float* w2       = (const float*)d_in[6];
    const float* b2       = (const float*)d_in[7];
    float* out = (float*)d_out;

    fused_conv_kernel<<<NP_ / 128, 128>>>(
        x, w1, bn_gamma, bn_beta, bn_mean, bn_var, w2, b2);

    involution_kernel<<<dim3(14, 16, 16), 256>>>(x, out);
}